// round 1
// baseline (speedup 1.0000x reference)
#include <cuda_runtime.h>
#include <cuda_bf16.h>
#include <math.h>

// Problem constants
#define B_    16384
#define DIN   512
#define DH    1024
#define KCAT  1536   // DH + DIN
#define N1    4096   // 4 stacked gates

// ---------------- scratch (__device__ globals: no allocation allowed) ------
__device__ float g_Acat [B_ * KCAT];     // [h_prev | x]           100 MB
__device__ float g_W1   [N1 * KCAT];     // [W?h | W?x] x4          25 MB
__device__ float g_C1   [B_ * N1];       // stage-1 preacts        268 MB
__device__ float g_prehx[B_ * DH];       // x @ W_x^T               64 MB
__device__ float g_s    [B_ * DH];       // s_t                     64 MB
__device__ float g_rh   [B_ * DH];       // r_t * h_prev            64 MB
__device__ float g_Tadd [B_ * DH];       // s_t @ WTs^T             64 MB
__device__ float g_ht   [B_ * DH];       // (r*h) @ W_h^T           64 MB

// ---------------- concat kernels -------------------------------------------
// Acat[b, 0:1024] = h_prev[b,:]; Acat[b, 1024:1536] = x[b,:]
__global__ void concat_A(const float* __restrict__ h, const float* __restrict__ x)
{
    int idx = blockIdx.x * blockDim.x + threadIdx.x;         // float4 index
    const int per_row = KCAT / 4;                            // 384
    if (idx >= B_ * per_row) return;
    int b  = idx / per_row;
    int c4 = idx - b * per_row;
    float4 v;
    if (c4 < DH / 4) v = ((const float4*)h)[b * (DH / 4) + c4];
    else             v = ((const float4*)x)[b * (DIN / 4) + (c4 - DH / 4)];
    ((float4*)g_Acat)[idx] = v;
}

// W1[n, 0:1024] = Wh_block[n%1024, :]; W1[n, 1024:1536] = Wx_block[n%1024, :]
__global__ void concat_W(const float* __restrict__ Wsh, const float* __restrict__ Wsx,
                         const float* __restrict__ WTh, const float* __restrict__ WTx,
                         const float* __restrict__ Wrh, const float* __restrict__ Wrx,
                         const float* __restrict__ Wzh, const float* __restrict__ Wzx)
{
    int idx = blockIdx.x * blockDim.x + threadIdx.x;
    const int per_row = KCAT / 4;                            // 384
    if (idx >= N1 * per_row) return;
    int n   = idx / per_row;
    int c4  = idx - n * per_row;
    int blk = n >> 10;
    int r   = n & (DH - 1);
    const float* Wh = (blk == 0) ? Wsh : (blk == 1) ? WTh : (blk == 2) ? Wrh : Wzh;
    const float* Wx = (blk == 0) ? Wsx : (blk == 1) ? WTx : (blk == 2) ? Wrx : Wzx;
    float4 v;
    if (c4 < DH / 4) v = ((const float4*)Wh)[r * (DH / 4) + c4];
    else             v = ((const float4*)Wx)[r * (DIN / 4) + (c4 - DH / 4)];
    ((float4*)g_W1)[idx] = v;
}

// ---------------- SGEMM: C[M,N] = A[M,K] @ W[N,K]^T ------------------------
// BM=BN=128, BK=16, 256 threads, 8x8 micro-tile. M,N %128==0, K %16==0.
#define BM 128
#define BN 128
#define BK 16
#define PAD 4      // keeps 16B alignment: (128+4)*4 = 528 = 33*16

__global__ __launch_bounds__(256, 2)
void sgemm_tn(const float* __restrict__ A, const float* __restrict__ W,
              float* __restrict__ C, int K, int ldc, int coff)
{
    __shared__ float As[BK][BM + PAD];
    __shared__ float Ws[BK][BN + PAD];

    const int t  = threadIdx.x;
    const int tx = t & 15;          // 0..15  (N direction)
    const int ty = t >> 4;          // 0..15  (M direction)
    const int m0 = blockIdx.y * BM;
    const int n0 = blockIdx.x * BN;

    float acc[8][8];
#pragma unroll
    for (int i = 0; i < 8; i++)
#pragma unroll
        for (int j = 0; j < 8; j++) acc[i][j] = 0.f;

    const int nk = K / BK;
    for (int kt = 0; kt < nk; kt++) {
        // load A tile: 512 float4, 2 per thread
#pragma unroll
        for (int i = 0; i < 2; i++) {
            int f   = t + i * 256;
            int r   = f >> 2;
            int kc4 = f & 3;
            float4 v = *(const float4*)&A[(size_t)(m0 + r) * K + kt * BK + kc4 * 4];
            As[kc4 * 4 + 0][r] = v.x;
            As[kc4 * 4 + 1][r] = v.y;
            As[kc4 * 4 + 2][r] = v.z;
            As[kc4 * 4 + 3][r] = v.w;
        }
        // load W tile
#pragma unroll
        for (int i = 0; i < 2; i++) {
            int f   = t + i * 256;
            int r   = f >> 2;
            int kc4 = f & 3;
            float4 v = *(const float4*)&W[(size_t)(n0 + r) * K + kt * BK + kc4 * 4];
            Ws[kc4 * 4 + 0][r] = v.x;
            Ws[kc4 * 4 + 1][r] = v.y;
            Ws[kc4 * 4 + 2][r] = v.z;
            Ws[kc4 * 4 + 3][r] = v.w;
        }
        __syncthreads();

#pragma unroll
        for (int k = 0; k < BK; k++) {
            float4 a0 = *(const float4*)&As[k][ty * 8];
            float4 a1 = *(const float4*)&As[k][ty * 8 + 4];
            float4 b0 = *(const float4*)&Ws[k][tx * 8];
            float4 b1 = *(const float4*)&Ws[k][tx * 8 + 4];
            float a[8] = {a0.x, a0.y, a0.z, a0.w, a1.x, a1.y, a1.z, a1.w};
            float b[8] = {b0.x, b0.y, b0.z, b0.w, b1.x, b1.y, b1.z, b1.w};
#pragma unroll
            for (int i = 0; i < 8; i++)
#pragma unroll
                for (int j = 0; j < 8; j++)
                    acc[i][j] = fmaf(a[i], b[j], acc[i][j]);
        }
        __syncthreads();
    }

    // store
#pragma unroll
    for (int i = 0; i < 8; i++) {
        float* crow = &C[(size_t)(m0 + ty * 8 + i) * ldc + coff + n0 + tx * 8];
        float4 v0 = {acc[i][0], acc[i][1], acc[i][2], acc[i][3]};
        float4 v1 = {acc[i][4], acc[i][5], acc[i][6], acc[i][7]};
        *(float4*)crow       = v0;
        *(float4*)(crow + 4) = v1;
    }
}

// ---------------- elementwise stages ---------------------------------------
__device__ __forceinline__ float sigm(float x) { return 1.f / (1.f + expf(-x)); }

// s_t = tanh(pre_s + delta*W_st + b_s); rh = sigmoid(pre_r + b_r) * h_prev
__global__ void ew1(const float* __restrict__ delta, const float* __restrict__ Wst,
                    const float* __restrict__ bs, const float* __restrict__ br,
                    const float* __restrict__ h)
{
    int idx = blockIdx.x * blockDim.x + threadIdx.x;
    if (idx >= B_ * DH) return;
    int b = idx >> 10;
    int n = idx & (DH - 1);
    float pre_s = g_C1[(size_t)b * N1 + n] + delta[b] * Wst[n] + bs[n];
    float pre_r = g_C1[(size_t)b * N1 + 2048 + n] + br[n];
    g_s[idx]  = tanhf(pre_s);
    g_rh[idx] = sigm(pre_r) * h[idx];
}

// T,z,h_tilde,h_t
__global__ void ew2(const float* __restrict__ bT, const float* __restrict__ bz,
                    const float* __restrict__ bb, const float* __restrict__ h,
                    float* __restrict__ out)
{
    int idx = blockIdx.x * blockDim.x + threadIdx.x;
    if (idx >= B_ * DH) return;
    int b = idx >> 10;
    int n = idx & (DH - 1);
    float T    = sigm(g_C1[(size_t)b * N1 + 1024 + n] + g_Tadd[idx] + bT[n]);
    float z    = sigm(g_C1[(size_t)b * N1 + 3072 + n] + bz[n]);
    float htil = tanhf(g_ht[idx] + g_prehx[idx] + bb[n]);
    out[idx]   = (1.f - z) * (T * h[idx]) + z * htil;
}

// ---------------- launch ----------------------------------------------------
extern "C" void kernel_launch(void* const* d_in, const int* in_sizes, int n_in,
                              void* d_out, int out_size)
{
    const float* x     = (const float*)d_in[0];
    const float* delta = (const float*)d_in[1];
    const float* h     = (const float*)d_in[2];
    const float* W_sh  = (const float*)d_in[3];
    const float* W_sx  = (const float*)d_in[4];
    const float* W_st  = (const float*)d_in[5];
    const float* b_s   = (const float*)d_in[6];
    const float* WTh   = (const float*)d_in[7];
    const float* WTx   = (const float*)d_in[8];
    const float* WTs   = (const float*)d_in[9];
    const float* b_T   = (const float*)d_in[10];
    const float* W_rh  = (const float*)d_in[11];
    const float* W_rx  = (const float*)d_in[12];
    const float* b_r   = (const float*)d_in[13];
    const float* W_zh  = (const float*)d_in[14];
    const float* W_zx  = (const float*)d_in[15];
    const float* b_z   = (const float*)d_in[16];
    const float* W_h   = (const float*)d_in[17];
    const float* W_x   = (const float*)d_in[18];
    const float* b     = (const float*)d_in[19];
    float* out = (float*)d_out;

    float *dAcat, *dW1, *dC1, *dprehx, *ds, *drh, *dTadd, *dht;
    cudaGetSymbolAddress((void**)&dAcat,  g_Acat);
    cudaGetSymbolAddress((void**)&dW1,    g_W1);
    cudaGetSymbolAddress((void**)&dC1,    g_C1);
    cudaGetSymbolAddress((void**)&dprehx, g_prehx);
    cudaGetSymbolAddress((void**)&ds,     g_s);
    cudaGetSymbolAddress((void**)&drh,    g_rh);
    cudaGetSymbolAddress((void**)&dTadd,  g_Tadd);
    cudaGetSymbolAddress((void**)&dht,    g_ht);

    // 1) concat inputs + weights
    {
        int nA = B_ * (KCAT / 4);
        concat_A<<<(nA + 255) / 256, 256>>>(h, x);
        int nW = N1 * (KCAT / 4);
        concat_W<<<(nW + 255) / 256, 256>>>(W_sh, W_sx, WTh, WTx, W_rh, W_rx, W_zh, W_zx);
    }

    // 2) stage-1 big GEMM: C1[16384,4096] = Acat @ W1^T
    sgemm_tn<<<dim3(N1 / BN, B_ / BM), 256>>>(dAcat, dW1, dC1, KCAT, N1, 0);

    // 3) pre_hx = x @ W_x^T   (K=512)
    sgemm_tn<<<dim3(DH / BN, B_ / BM), 256>>>(x, W_x, dprehx, DIN, DH, 0);

    // 4) s_t, r*h
    ew1<<<(B_ * DH + 255) / 256, 256>>>(delta, W_st, b_s, b_r, h);

    // 5) Tadd = s @ WTs^T ;  ht = (r*h) @ W_h^T
    sgemm_tn<<<dim3(DH / BN, B_ / BM), 256>>>(ds,  WTs, dTadd, DH, DH, 0);
    sgemm_tn<<<dim3(DH / BN, B_ / BM), 256>>>(drh, W_h, dht,   DH, DH, 0);

    // 6) final gate math
    ew2<<<(B_ * DH + 255) / 256, 256>>>(b_T, b_z, b, h, out);
}

// round 3
// speedup vs baseline: 2.2724x; 2.2724x over previous
#include <cuda_runtime.h>
#include <cuda_bf16.h>
#include <cstdint>
#include <math.h>

#define B_    16384
#define DIN   512
#define DH    1024

// K2 dims (tripled hi/lo split): stage1 = 3*1536, x-gemm = 3*512, h-gemms = 3*1024
#define K2_S1 4608
#define K2_X  1536
#define K2_H  3072
#define N1    4096

// ---------------- scratch --------------------------------------------------
__device__ __nv_bfloat16 g_A2 [(size_t)B_ * K2_S1];   // [hi(h|x) | hi(h|x) | lo(h|x)]
__device__ __nv_bfloat16 g_W2 [(size_t)N1 * K2_S1];   // [hi | lo | hi] of 4 stacked gates
__device__ __nv_bfloat16 g_x2 [(size_t)B_ * K2_X];
__device__ __nv_bfloat16 g_Wx2[(size_t)DH * K2_X];
__device__ __nv_bfloat16 g_s2 [(size_t)B_ * K2_H];
__device__ __nv_bfloat16 g_rh2[(size_t)B_ * K2_H];
__device__ __nv_bfloat16 g_Ws2[(size_t)DH * K2_H];
__device__ __nv_bfloat16 g_Wh2[(size_t)DH * K2_H];
__device__ float g_C1   [(size_t)B_ * N1];
__device__ float g_prehx[(size_t)B_ * DH];
__device__ float g_Tadd [(size_t)B_ * DH];
__device__ float g_ht   [(size_t)B_ * DH];

// ---------------- mma/ldmatrix/cp.async helpers (sm_80-era, sm_103-safe) ----
__device__ __forceinline__ uint32_t smem_u32(const void* p) {
    uint32_t a;
    asm("{ .reg .u64 t; cvta.to.shared.u64 t, %1; cvt.u32.u64 %0, t; }" : "=r"(a) : "l"(p));
    return a;
}
__device__ __forceinline__ void cp16(uint32_t sdst, const void* gsrc) {
    asm volatile("cp.async.cg.shared.global [%0], [%1], 16;" :: "r"(sdst), "l"(gsrc));
}
__device__ __forceinline__ void ldsm4(uint32_t* r, uint32_t addr) {
    asm volatile("ldmatrix.sync.aligned.m8n8.x4.shared.b16 {%0,%1,%2,%3}, [%4];"
                 : "=r"(r[0]), "=r"(r[1]), "=r"(r[2]), "=r"(r[3]) : "r"(addr));
}
__device__ __forceinline__ void mma16816(float* d, const uint32_t* a, uint32_t b0, uint32_t b1) {
    asm volatile("mma.sync.aligned.m16n8k16.row.col.f32.bf16.bf16.f32 "
                 "{%0,%1,%2,%3}, {%4,%5,%6,%7}, {%8,%9}, {%0,%1,%2,%3};"
                 : "+f"(d[0]), "+f"(d[1]), "+f"(d[2]), "+f"(d[3])
                 : "r"(a[0]), "r"(a[1]), "r"(a[2]), "r"(a[3]), "r"(b0), "r"(b1));
}

// ---------------- HMMA GEMM: C[M,N] = A[M,K2] @ W[N,K2]^T -------------------
// CTA 128(M) x 256(N), BK=64 bf16 (128B SW128 rows), 512 thr, 3-stage cp.async.
#define NTHR 512
#define ST_A_BYTES (128 * 128)           // 16 KB
#define ST_B_BYTES (256 * 128)           // 32 KB
#define ST_STRIDE  (ST_A_BYTES + ST_B_BYTES)   // 48 KB
#define STAGES 3
#define SM_TOT (STAGES * ST_STRIDE)      // 144 KB

__device__ __forceinline__ void load_tile(const __nv_bfloat16* __restrict__ A,
                                          const __nv_bfloat16* __restrict__ W,
                                          int K2, int m0, int n0,
                                          uint32_t sbase, int stage, int it, int tid)
{
    const size_t k0 = (size_t)it * 64;
    const uint32_t sA = sbase + stage * ST_STRIDE;
    const uint32_t sB = sA + ST_A_BYTES;
#pragma unroll
    for (int j = 0; j < 6; ++j) {
        int f = tid + j * NTHR;                  // 0..3071 (1024 A chunks, 2048 B chunks)
        if (f < 1024) {
            int row = f >> 3, c = f & 7;
            cp16(sA + row * 128 + ((c ^ (row & 7)) << 4),
                 A + (size_t)(m0 + row) * K2 + k0 + c * 8);
        } else {
            int f2 = f - 1024, row = f2 >> 3, c = f2 & 7;
            cp16(sB + row * 128 + ((c ^ (row & 7)) << 4),
                 W + (size_t)(n0 + row) * K2 + k0 + c * 8);
        }
    }
}

__global__ __launch_bounds__(NTHR)
void gemm_mma(const __nv_bfloat16* __restrict__ A, const __nv_bfloat16* __restrict__ W,
              float* __restrict__ C, int K2, int ldc)
{
    extern __shared__ __align__(1024) char smem[];
    const uint32_t sbase = smem_u32(smem);
    const int tid = threadIdx.x;
    const int wid = tid >> 5, lane = tid & 31;
    const int wm = (wid & 3) * 32;          // warp M offset (4 warps in M)
    const int wn = (wid >> 2) * 64;         // warp N offset (4 warps in N)
    const int m0 = blockIdx.y * 128;
    const int n0 = blockIdx.x * 256;
    const int T  = K2 >> 6;

    float acc[2][8][4];
#pragma unroll
    for (int i = 0; i < 2; i++)
#pragma unroll
        for (int j = 0; j < 8; j++)
#pragma unroll
            for (int k = 0; k < 4; k++) acc[i][j][k] = 0.f;

    // prefetch STAGES-1 tiles
#pragma unroll
    for (int it = 0; it < STAGES - 1; ++it) {
        load_tile(A, W, K2, m0, n0, sbase, it, it, tid);
        asm volatile("cp.async.commit_group;" ::: "memory");
    }

    const int la = lane & 15;         // ldmatrix row-within-16
    const int lk = lane >> 4;         // k-half select

    for (int it = 0; it < T; ++it) {
        asm volatile("cp.async.wait_group 1;" ::: "memory");
        __syncthreads();

        int pf = it + STAGES - 1;
        if (pf < T) load_tile(A, W, K2, m0, n0, sbase, pf % STAGES, pf, tid);
        asm volatile("cp.async.commit_group;" ::: "memory");

        const uint32_t aA = sbase + (it % STAGES) * ST_STRIDE;
        const uint32_t aB = aA + ST_A_BYTES;

#pragma unroll
        for (int ks = 0; ks < 4; ++ks) {
            const int c = ks * 2 + lk;                 // 16B chunk index in row
            uint32_t af[2][4];
#pragma unroll
            for (int mi = 0; mi < 2; ++mi) {
                int row = wm + mi * 16 + la;
                ldsm4(af[mi], aA + row * 128 + ((c ^ (row & 7)) << 4));
            }
            uint32_t bfr[4][4];
#pragma unroll
            for (int nb = 0; nb < 4; ++nb) {
                int row = wn + nb * 16 + la;
                ldsm4(bfr[nb], aB + row * 128 + ((c ^ (row & 7)) << 4));
            }
#pragma unroll
            for (int mi = 0; mi < 2; ++mi)
#pragma unroll
                for (int nb = 0; nb < 4; ++nb) {
                    mma16816(acc[mi][nb * 2 + 0], af[mi], bfr[nb][0], bfr[nb][2]);
                    mma16816(acc[mi][nb * 2 + 1], af[mi], bfr[nb][1], bfr[nb][3]);
                }
        }
    }

    // epilogue: standard m16n8 fragment layout
#pragma unroll
    for (int mi = 0; mi < 2; ++mi) {
        int r0 = m0 + wm + mi * 16 + (lane >> 2);
#pragma unroll
        for (int ni = 0; ni < 8; ++ni) {
            int col = n0 + wn + ni * 8 + (lane & 3) * 2;
            float2 v0 = { acc[mi][ni][0], acc[mi][ni][1] };
            float2 v1 = { acc[mi][ni][2], acc[mi][ni][3] };
            *(float2*)(C + (size_t)r0 * ldc + col)       = v0;
            *(float2*)(C + (size_t)(r0 + 8) * ldc + col) = v1;
        }
    }
}

// ---------------- hi/lo split helpers --------------------------------------
__device__ __forceinline__ void split2(float v, __nv_bfloat16& hi, __nv_bfloat16& lo) {
    hi = __float2bfloat16(v);
    lo = __float2bfloat16(v - __bfloat162float(hi));
}

__global__ void convA2(const float* __restrict__ h, const float* __restrict__ x)
{
    int idx = blockIdx.x * blockDim.x + threadIdx.x;
    if (idx >= B_ * 1536) return;
    int b = idx / 1536, c = idx - b * 1536;
    float v = (c < DH) ? h[(size_t)b * DH + c] : x[(size_t)b * DIN + c - DH];
    __nv_bfloat16 hi, lo; split2(v, hi, lo);
    size_t base = (size_t)b * K2_S1 + c;
    g_A2[base] = hi; g_A2[base + 1536] = hi; g_A2[base + 3072] = lo;
}

__global__ void convW2(const float* __restrict__ Wsh, const float* __restrict__ Wsx,
                       const float* __restrict__ WTh, const float* __restrict__ WTx,
                       const float* __restrict__ Wrh, const float* __restrict__ Wrx,
                       const float* __restrict__ Wzh, const float* __restrict__ Wzx)
{
    int idx = blockIdx.x * blockDim.x + threadIdx.x;
    if (idx >= N1 * 1536) return;
    int n = idx / 1536, c = idx - n * 1536;
    int blk = n >> 10, r = n & (DH - 1);
    const float* Wh = (blk == 0) ? Wsh : (blk == 1) ? WTh : (blk == 2) ? Wrh : Wzh;
    const float* Wx = (blk == 0) ? Wsx : (blk == 1) ? WTx : (blk == 2) ? Wrx : Wzx;
    float v = (c < DH) ? Wh[(size_t)r * DH + c] : Wx[(size_t)r * DIN + c - DH];
    __nv_bfloat16 hi, lo; split2(v, hi, lo);
    size_t base = (size_t)n * K2_S1 + c;
    g_W2[base] = hi; g_W2[base + 1536] = lo; g_W2[base + 3072] = hi;
}

__global__ void convX2(const float* __restrict__ x)
{
    int idx = blockIdx.x * blockDim.x + threadIdx.x;
    if (idx >= B_ * DIN) return;
    int b = idx / DIN, c = idx - b * DIN;
    __nv_bfloat16 hi, lo; split2(x[idx], hi, lo);
    size_t base = (size_t)b * K2_X + c;
    g_x2[base] = hi; g_x2[base + 512] = hi; g_x2[base + 1024] = lo;
}

__global__ void convWx2(const float* __restrict__ Wx)
{
    int idx = blockIdx.x * blockDim.x + threadIdx.x;
    if (idx >= DH * DIN) return;
    int n = idx / DIN, c = idx - n * DIN;
    __nv_bfloat16 hi, lo; split2(Wx[idx], hi, lo);
    size_t base = (size_t)n * K2_X + c;
    g_Wx2[base] = hi; g_Wx2[base + 512] = lo; g_Wx2[base + 1024] = hi;
}

__global__ void convWs(const float* __restrict__ Wsrc, __nv_bfloat16* __restrict__ out)
{
    int idx = blockIdx.x * blockDim.x + threadIdx.x;
    if (idx >= DH * DH) return;
    int n = idx / DH, c = idx - n * DH;
    __nv_bfloat16 hi, lo; split2(Wsrc[idx], hi, lo);
    size_t base = (size_t)n * K2_H + c;
    out[base] = hi; out[base + 1024] = lo; out[base + 2048] = hi;
}

// ---------------- elementwise stages ---------------------------------------
__device__ __forceinline__ float sigm(float x) { return 1.f / (1.f + expf(-x)); }

__global__ void ew1(const float* __restrict__ delta, const float* __restrict__ Wst,
                    const float* __restrict__ bs, const float* __restrict__ br,
                    const float* __restrict__ h)
{
    int idx = blockIdx.x * blockDim.x + threadIdx.x;
    if (idx >= B_ * DH) return;
    int b = idx >> 10, n = idx & (DH - 1);
    float pre_s = g_C1[(size_t)b * N1 + n] + delta[b] * Wst[n] + bs[n];
    float pre_r = g_C1[(size_t)b * N1 + 2048 + n] + br[n];
    float sv = tanhf(pre_s);
    float rh = sigm(pre_r) * h[idx];
    __nv_bfloat16 hi, lo;
    size_t base = (size_t)b * K2_H + n;
    split2(sv, hi, lo); g_s2[base] = hi;  g_s2[base + 1024] = hi;  g_s2[base + 2048] = lo;
    split2(rh, hi, lo); g_rh2[base] = hi; g_rh2[base + 1024] = hi; g_rh2[base + 2048] = lo;
}

__global__ void ew2(const float* __restrict__ bT, const float* __restrict__ bz,
                    const float* __restrict__ bb, const float* __restrict__ h,
                    float* __restrict__ out)
{
    int idx = blockIdx.x * blockDim.x + threadIdx.x;
    if (idx >= B_ * DH) return;
    int b = idx >> 10, n = idx & (DH - 1);
    float T    = sigm(g_C1[(size_t)b * N1 + 1024 + n] + g_Tadd[idx] + bT[n]);
    float z    = sigm(g_C1[(size_t)b * N1 + 3072 + n] + bz[n]);
    float htil = tanhf(g_ht[idx] + g_prehx[idx] + bb[n]);
    out[idx]   = (1.f - z) * (T * h[idx]) + z * htil;
}

// ---------------- launch ----------------------------------------------------
extern "C" void kernel_launch(void* const* d_in, const int* in_sizes, int n_in,
                              void* d_out, int out_size)
{
    const float* x     = (const float*)d_in[0];
    const float* delta = (const float*)d_in[1];
    const float* h     = (const float*)d_in[2];
    const float* W_sh  = (const float*)d_in[3];
    const float* W_sx  = (const float*)d_in[4];
    const float* W_st  = (const float*)d_in[5];
    const float* b_s   = (const float*)d_in[6];
    const float* WTh   = (const float*)d_in[7];
    const float* WTx   = (const float*)d_in[8];
    const float* WTs   = (const float*)d_in[9];
    const float* b_T   = (const float*)d_in[10];
    const float* W_rh  = (const float*)d_in[11];
    const float* W_rx  = (const float*)d_in[12];
    const float* b_r   = (const float*)d_in[13];
    const float* W_zh  = (const float*)d_in[14];
    const float* W_zx  = (const float*)d_in[15];
    const float* b_z   = (const float*)d_in[16];
    const float* W_h   = (const float*)d_in[17];
    const float* W_x   = (const float*)d_in[18];
    const float* b     = (const float*)d_in[19];
    float* out = (float*)d_out;

    cudaFuncSetAttribute(gemm_mma, cudaFuncAttributeMaxDynamicSharedMemorySize, SM_TOT);

    __nv_bfloat16 *dA2, *dW2, *dx2, *dWx2, *ds2, *drh2, *dWs2, *dWh2;
    float *dC1, *dprehx, *dTadd, *dht;
    cudaGetSymbolAddress((void**)&dA2,  g_A2);
    cudaGetSymbolAddress((void**)&dW2,  g_W2);
    cudaGetSymbolAddress((void**)&dx2,  g_x2);
    cudaGetSymbolAddress((void**)&dWx2, g_Wx2);
    cudaGetSymbolAddress((void**)&ds2,  g_s2);
    cudaGetSymbolAddress((void**)&drh2, g_rh2);
    cudaGetSymbolAddress((void**)&dWs2, g_Ws2);
    cudaGetSymbolAddress((void**)&dWh2, g_Wh2);
    cudaGetSymbolAddress((void**)&dC1,   g_C1);
    cudaGetSymbolAddress((void**)&dprehx,g_prehx);
    cudaGetSymbolAddress((void**)&dTadd, g_Tadd);
    cudaGetSymbolAddress((void**)&dht,   g_ht);

    // 1) hi/lo conversions
    convA2 <<<(B_ * 1536 + 255) / 256, 256>>>(h, x);
    convW2 <<<(N1 * 1536 + 255) / 256, 256>>>(W_sh, W_sx, WTh, WTx, W_rh, W_rx, W_zh, W_zx);
    convX2 <<<(B_ * DIN + 255) / 256, 256>>>(x);
    convWx2<<<(DH * DIN + 255) / 256, 256>>>(W_x);
    convWs <<<(DH * DH + 255) / 256, 256>>>(WTs, dWs2);
    convWs <<<(DH * DH + 255) / 256, 256>>>(W_h, dWh2);

    // 2) stage-1: C1[16384,4096] = A2 @ W2^T   (K2=4608)
    gemm_mma<<<dim3(N1 / 256, B_ / 128), NTHR, SM_TOT>>>(dA2, dW2, dC1, K2_S1, N1);

    // 3) prehx = x2 @ Wx2^T   (K2=1536)
    gemm_mma<<<dim3(DH / 256, B_ / 128), NTHR, SM_TOT>>>(dx2, dWx2, dprehx, K2_X, DH);

    // 4) s_t, r*h (writes hi/lo bf16 operands)
    ew1<<<(B_ * DH + 255) / 256, 256>>>(delta, W_st, b_s, b_r, h);

    // 5) Tadd = s2 @ Ws2^T ; ht = rh2 @ Wh2^T   (K2=3072)
    gemm_mma<<<dim3(DH / 256, B_ / 128), NTHR, SM_TOT>>>(ds2,  dWs2, dTadd, K2_H, DH);
    gemm_mma<<<dim3(DH / 256, B_ / 128), NTHR, SM_TOT>>>(drh2, dWh2, dht,   K2_H, DH);

    // 6) final gates
    ew2<<<(B_ * DH + 255) / 256, 256>>>(b_T, b_z, b, h, out);
}

// round 4
// speedup vs baseline: 2.2802x; 1.0034x over previous
#include <cuda_runtime.h>
#include <cuda_bf16.h>
#include <cstdint>
#include <math.h>

#define B_    16384
#define DIN   512
#define DH    1024

// K2 dims (tripled hi/lo split)
#define K2_S1 4608
#define K2_X  1536
#define K2_H  3072
#define N1    4096

// ---------------- scratch --------------------------------------------------
__device__ __nv_bfloat16 g_A2 [(size_t)B_ * K2_S1];   // [hi(h|x) | hi(h|x) | lo(h|x)]
__device__ __nv_bfloat16 g_W2 [(size_t)N1 * K2_S1];   // [hi | lo | hi] of 4 stacked gates
__device__ __nv_bfloat16 g_x2 [(size_t)B_ * K2_X];
__device__ __nv_bfloat16 g_Wx2[(size_t)DH * K2_X];
__device__ __nv_bfloat16 g_s2 [(size_t)B_ * K2_H];
__device__ __nv_bfloat16 g_rh2[(size_t)B_ * K2_H];
__device__ __nv_bfloat16 g_Ws2[(size_t)DH * K2_H];
__device__ __nv_bfloat16 g_Wh2[(size_t)DH * K2_H];
__device__ float g_C1   [(size_t)B_ * N1];    // only gates 1 (T) and 3 (z) written
__device__ float g_prehx[(size_t)B_ * DH];
__device__ float g_Tadd [(size_t)B_ * DH];

// ---------------- mma/ldmatrix/cp.async helpers -----------------------------
__device__ __forceinline__ uint32_t smem_u32(const void* p) {
    uint32_t a;
    asm("{ .reg .u64 t; cvta.to.shared.u64 t, %1; cvt.u32.u64 %0, t; }" : "=r"(a) : "l"(p));
    return a;
}
__device__ __forceinline__ void cp16(uint32_t sdst, const void* gsrc) {
    asm volatile("cp.async.cg.shared.global [%0], [%1], 16;" :: "r"(sdst), "l"(gsrc));
}
__device__ __forceinline__ void ldsm4(uint32_t* r, uint32_t addr) {
    asm volatile("ldmatrix.sync.aligned.m8n8.x4.shared.b16 {%0,%1,%2,%3}, [%4];"
                 : "=r"(r[0]), "=r"(r[1]), "=r"(r[2]), "=r"(r[3]) : "r"(addr));
}
__device__ __forceinline__ void mma16816(float* d, const uint32_t* a, uint32_t b0, uint32_t b1) {
    asm volatile("mma.sync.aligned.m16n8k16.row.col.f32.bf16.bf16.f32 "
                 "{%0,%1,%2,%3}, {%4,%5,%6,%7}, {%8,%9}, {%0,%1,%2,%3};"
                 : "+f"(d[0]), "+f"(d[1]), "+f"(d[2]), "+f"(d[3])
                 : "r"(a[0]), "r"(a[1]), "r"(a[2]), "r"(a[3]), "r"(b0), "r"(b1));
}

// ---------------- shared GEMM core: acc = A[M,K2] @ W[N,K2]^T tile ----------
#define NTHR 512
#define ST_A_BYTES (128 * 128)
#define ST_B_BYTES (256 * 128)
#define ST_STRIDE  (ST_A_BYTES + ST_B_BYTES)
#define STAGES 3
#define SM_TOT (STAGES * ST_STRIDE)      // 144 KB

__device__ __forceinline__ void load_tile(const __nv_bfloat16* __restrict__ A,
                                          const __nv_bfloat16* __restrict__ W,
                                          int K2, int m0, int n0,
                                          uint32_t sbase, int stage, int it, int tid)
{
    const size_t k0 = (size_t)it * 64;
    const uint32_t sA = sbase + stage * ST_STRIDE;
    const uint32_t sB = sA + ST_A_BYTES;
#pragma unroll
    for (int j = 0; j < 6; ++j) {
        int f = tid + j * NTHR;
        if (f < 1024) {
            int row = f >> 3, c = f & 7;
            cp16(sA + row * 128 + ((c ^ (row & 7)) << 4),
                 A + (size_t)(m0 + row) * K2 + k0 + c * 8);
        } else {
            int f2 = f - 1024, row = f2 >> 3, c = f2 & 7;
            cp16(sB + row * 128 + ((c ^ (row & 7)) << 4),
                 W + (size_t)(n0 + row) * K2 + k0 + c * 8);
        }
    }
}

__device__ __forceinline__ void gemm_core(const __nv_bfloat16* __restrict__ A,
                                          const __nv_bfloat16* __restrict__ W,
                                          int K2, int m0, int n0,
                                          uint32_t sbase, int tid,
                                          float acc[2][8][4])
{
    const int wid = tid >> 5, lane = tid & 31;
    const int wm = (wid & 3) * 32;
    const int wn = (wid >> 2) * 64;
    const int T  = K2 >> 6;

#pragma unroll
    for (int i = 0; i < 2; i++)
#pragma unroll
        for (int j = 0; j < 8; j++)
#pragma unroll
            for (int k = 0; k < 4; k++) acc[i][j][k] = 0.f;

#pragma unroll
    for (int it = 0; it < STAGES - 1; ++it) {
        load_tile(A, W, K2, m0, n0, sbase, it, it, tid);
        asm volatile("cp.async.commit_group;" ::: "memory");
    }

    const int la = lane & 15;
    const int lk = lane >> 4;

    for (int it = 0; it < T; ++it) {
        asm volatile("cp.async.wait_group 1;" ::: "memory");
        __syncthreads();

        int pf = it + STAGES - 1;
        if (pf < T) load_tile(A, W, K2, m0, n0, sbase, pf % STAGES, pf, tid);
        asm volatile("cp.async.commit_group;" ::: "memory");

        const uint32_t aA = sbase + (it % STAGES) * ST_STRIDE;
        const uint32_t aB = aA + ST_A_BYTES;

#pragma unroll
        for (int ks = 0; ks < 4; ++ks) {
            const int c = ks * 2 + lk;
            uint32_t af[2][4];
#pragma unroll
            for (int mi = 0; mi < 2; ++mi) {
                int row = wm + mi * 16 + la;
                ldsm4(af[mi], aA + row * 128 + ((c ^ (row & 7)) << 4));
            }
            uint32_t bfr[4][4];
#pragma unroll
            for (int nb = 0; nb < 4; ++nb) {
                int row = wn + nb * 16 + la;
                ldsm4(bfr[nb], aB + row * 128 + ((c ^ (row & 7)) << 4));
            }
#pragma unroll
            for (int mi = 0; mi < 2; ++mi)
#pragma unroll
                for (int nb = 0; nb < 4; ++nb) {
                    mma16816(acc[mi][nb * 2 + 0], af[mi], bfr[nb][0], bfr[nb][2]);
                    mma16816(acc[mi][nb * 2 + 1], af[mi], bfr[nb][1], bfr[nb][3]);
                }
        }
    }
}

// ---------------- math helpers ---------------------------------------------
__device__ __forceinline__ float sigm(float x) { return 1.f / (1.f + expf(-x)); }
__device__ __forceinline__ void split2(float v, __nv_bfloat16& hi, __nv_bfloat16& lo) {
    hi = __float2bfloat16(v);
    lo = __float2bfloat16(v - __bfloat162float(hi));
}
// write hi/hi/lo triple for a pair of adjacent columns (4B stores)
__device__ __forceinline__ void store_split_pair(__nv_bfloat16* dst, size_t base,
                                                 float v0, float v1)
{
    __nv_bfloat16 h0, l0, h1, l1;
    split2(v0, h0, l0); split2(v1, h1, l1);
    __nv_bfloat162 hh; hh.x = h0; hh.y = h1;
    __nv_bfloat162 ll; ll.x = l0; ll.y = l1;
    *(__nv_bfloat162*)(dst + base)        = hh;
    *(__nv_bfloat162*)(dst + base + 1024) = hh;
    *(__nv_bfloat162*)(dst + base + 2048) = ll;
}

// ---------------- stage-1 GEMM with fused ew1 epilogue ----------------------
// gate = n0>>10: 0 -> s_t path (g_s2), 1 -> C1, 2 -> r*h path (g_rh2), 3 -> C1
__global__ __launch_bounds__(NTHR)
void gemm_s1_fused(const __nv_bfloat16* __restrict__ A, const __nv_bfloat16* __restrict__ W,
                   float* __restrict__ C,
                   const float* __restrict__ delta, const float* __restrict__ Wst,
                   const float* __restrict__ bs, const float* __restrict__ br,
                   const float* __restrict__ h)
{
    extern __shared__ __align__(1024) char smem[];
    const uint32_t sbase = smem_u32(smem);
    const int tid = threadIdx.x;
    const int m0 = blockIdx.y * 128;
    const int n0 = blockIdx.x * 256;

    float acc[2][8][4];
    gemm_core(A, W, K2_S1, m0, n0, sbase, tid, acc);

    const int wid = tid >> 5, lane = tid & 31;
    const int wm = (wid & 3) * 32;
    const int wn = (wid >> 2) * 64;
    const int gate = n0 >> 10;

#pragma unroll
    for (int mi = 0; mi < 2; ++mi) {
#pragma unroll
        for (int rr = 0; rr < 2; ++rr) {
            const int row = m0 + wm + mi * 16 + (lane >> 2) + rr * 8;   // batch index b
            const float dv = (gate == 0) ? delta[row] : 0.f;
#pragma unroll
            for (int ni = 0; ni < 8; ++ni) {
                const int colg = n0 + wn + ni * 8 + (lane & 3) * 2;     // global col
                const int ng   = colg & 1023;                           // col within gate
                float v0 = acc[mi][ni][rr * 2 + 0];
                float v1 = acc[mi][ni][rr * 2 + 1];
                if (gate == 0) {
                    float s0 = tanhf(v0 + dv * Wst[ng]     + bs[ng]);
                    float s1 = tanhf(v1 + dv * Wst[ng + 1] + bs[ng + 1]);
                    store_split_pair(g_s2, (size_t)row * K2_H + ng, s0, s1);
                } else if (gate == 2) {
                    float r0 = sigm(v0 + br[ng])     * h[(size_t)row * DH + ng];
                    float r1 = sigm(v1 + br[ng + 1]) * h[(size_t)row * DH + ng + 1];
                    store_split_pair(g_rh2, (size_t)row * K2_H + ng, r0, r1);
                } else {
                    float2 v = { v0, v1 };
                    *(float2*)(C + (size_t)row * N1 + colg) = v;
                }
            }
        }
    }
}

// ---------------- plain GEMM (x-gemm, Tadd) ---------------------------------
__global__ __launch_bounds__(NTHR)
void gemm_plain(const __nv_bfloat16* __restrict__ A, const __nv_bfloat16* __restrict__ W,
                float* __restrict__ C, int K2, int ldc)
{
    extern __shared__ __align__(1024) char smem[];
    const uint32_t sbase = smem_u32(smem);
    const int tid = threadIdx.x;
    const int m0 = blockIdx.y * 128;
    const int n0 = blockIdx.x * 256;

    float acc[2][8][4];
    gemm_core(A, W, K2, m0, n0, sbase, tid, acc);

    const int wid = tid >> 5, lane = tid & 31;
    const int wm = (wid & 3) * 32;
    const int wn = (wid >> 2) * 64;
#pragma unroll
    for (int mi = 0; mi < 2; ++mi) {
        int r0 = m0 + wm + mi * 16 + (lane >> 2);
#pragma unroll
        for (int ni = 0; ni < 8; ++ni) {
            int col = n0 + wn + ni * 8 + (lane & 3) * 2;
            float2 v0 = { acc[mi][ni][0], acc[mi][ni][1] };
            float2 v1 = { acc[mi][ni][2], acc[mi][ni][3] };
            *(float2*)(C + (size_t)r0 * ldc + col)       = v0;
            *(float2*)(C + (size_t)(r0 + 8) * ldc + col) = v1;
        }
    }
}

// ---------------- ht GEMM with fused ew2 epilogue ---------------------------
// acc = (r*h) @ W_h^T ; out = (1-z)*(T*h) + z*tanh(acc + prehx + b)
__global__ __launch_bounds__(NTHR)
void gemm_ht_fused(const __nv_bfloat16* __restrict__ A, const __nv_bfloat16* __restrict__ W,
                   const float* __restrict__ bT, const float* __restrict__ bz,
                   const float* __restrict__ bb, const float* __restrict__ h,
                   float* __restrict__ out)
{
    extern __shared__ __align__(1024) char smem[];
    const uint32_t sbase = smem_u32(smem);
    const int tid = threadIdx.x;
    const int m0 = blockIdx.y * 128;
    const int n0 = blockIdx.x * 256;

    float acc[2][8][4];
    gemm_core(A, W, K2_H, m0, n0, sbase, tid, acc);

    const int wid = tid >> 5, lane = tid & 31;
    const int wm = (wid & 3) * 32;
    const int wn = (wid >> 2) * 64;

#pragma unroll
    for (int mi = 0; mi < 2; ++mi) {
#pragma unroll
        for (int rr = 0; rr < 2; ++rr) {
            const int row = m0 + wm + mi * 16 + (lane >> 2) + rr * 8;
#pragma unroll
            for (int ni = 0; ni < 8; ++ni) {
                const int ng = n0 + wn + ni * 8 + (lane & 3) * 2;
                const size_t e0 = (size_t)row * DH + ng;
                const size_t c0 = (size_t)row * N1 + ng;
                float v0 = acc[mi][ni][rr * 2 + 0];
                float v1 = acc[mi][ni][rr * 2 + 1];
                float T0 = sigm(g_C1[c0 + 1024]     + g_Tadd[e0]     + bT[ng]);
                float T1 = sigm(g_C1[c0 + 1025]     + g_Tadd[e0 + 1] + bT[ng + 1]);
                float z0 = sigm(g_C1[c0 + 3072]     + bz[ng]);
                float z1 = sigm(g_C1[c0 + 3073]     + bz[ng + 1]);
                float t0 = tanhf(v0 + g_prehx[e0]     + bb[ng]);
                float t1 = tanhf(v1 + g_prehx[e0 + 1] + bb[ng + 1]);
                float2 o;
                o.x = (1.f - z0) * (T0 * h[e0])     + z0 * t0;
                o.y = (1.f - z1) * (T1 * h[e0 + 1]) + z1 * t1;
                *(float2*)(out + e0) = o;
            }
        }
    }
}

// ---------------- fused conversion kernels ----------------------------------
// all weights in one launch
#define NW2  (N1 * 1536)
#define NWX  (DH * DIN)
#define NWH  (DH * DH)
__global__ void convW_all(const float* __restrict__ Wsh, const float* __restrict__ Wsx,
                          const float* __restrict__ WTh, const float* __restrict__ WTx,
                          const float* __restrict__ Wrh, const float* __restrict__ Wrx,
                          const float* __restrict__ Wzh, const float* __restrict__ Wzx,
                          const float* __restrict__ Wx,  const float* __restrict__ WTs,
                          const float* __restrict__ Wh)
{
    int idx = blockIdx.x * blockDim.x + threadIdx.x;
    if (idx < NW2) {
        int n = idx / 1536, c = idx - n * 1536;
        int blk = n >> 10, r = n & (DH - 1);
        const float* Ph = (blk == 0) ? Wsh : (blk == 1) ? WTh : (blk == 2) ? Wrh : Wzh;
        const float* Px = (blk == 0) ? Wsx : (blk == 1) ? WTx : (blk == 2) ? Wrx : Wzx;
        float v = (c < DH) ? Ph[(size_t)r * DH + c] : Px[(size_t)r * DIN + c - DH];
        __nv_bfloat16 hi, lo; split2(v, hi, lo);
        size_t base = (size_t)n * K2_S1 + c;
        g_W2[base] = hi; g_W2[base + 1536] = lo; g_W2[base + 3072] = hi;
        return;
    }
    idx -= NW2;
    if (idx < NWX) {
        int n = idx / DIN, c = idx - n * DIN;
        __nv_bfloat16 hi, lo; split2(Wx[idx], hi, lo);
        size_t base = (size_t)n * K2_X + c;
        g_Wx2[base] = hi; g_Wx2[base + 512] = lo; g_Wx2[base + 1024] = hi;
        return;
    }
    idx -= NWX;
    if (idx < NWH) {
        int n = idx / DH, c = idx - n * DH;
        __nv_bfloat16 hi, lo; split2(WTs[idx], hi, lo);
        size_t base = (size_t)n * K2_H + c;
        g_Ws2[base] = hi; g_Ws2[base + 1024] = lo; g_Ws2[base + 2048] = hi;
        return;
    }
    idx -= NWH;
    if (idx < NWH) {
        int n = idx / DH, c = idx - n * DH;
        __nv_bfloat16 hi, lo; split2(Wh[idx], hi, lo);
        size_t base = (size_t)n * K2_H + c;
        g_Wh2[base] = hi; g_Wh2[base + 1024] = lo; g_Wh2[base + 2048] = hi;
    }
}
#define NW_ALL (NW2 + NWX + NWH + NWH)

// activations: A2 ([h|x] split) + x2
#define NA2 (B_ * 1536)
#define NX2 (B_ * DIN)
__global__ void convAct(const float* __restrict__ h, const float* __restrict__ x)
{
    int idx = blockIdx.x * blockDim.x + threadIdx.x;
    if (idx < NA2) {
        int b = idx / 1536, c = idx - b * 1536;
        float v = (c < DH) ? h[(size_t)b * DH + c] : x[(size_t)b * DIN + c - DH];
        __nv_bfloat16 hi, lo; split2(v, hi, lo);
        size_t base = (size_t)b * K2_S1 + c;
        g_A2[base] = hi; g_A2[base + 1536] = hi; g_A2[base + 3072] = lo;
        return;
    }
    idx -= NA2;
    if (idx < NX2) {
        int b = idx / DIN, c = idx - b * DIN;
        __nv_bfloat16 hi, lo; split2(x[idx], hi, lo);
        size_t base = (size_t)b * K2_X + c;
        g_x2[base] = hi; g_x2[base + 512] = hi; g_x2[base + 1024] = lo;
    }
}
#define NACT (NA2 + NX2)

// ---------------- launch ----------------------------------------------------
extern "C" void kernel_launch(void* const* d_in, const int* in_sizes, int n_in,
                              void* d_out, int out_size)
{
    const float* x     = (const float*)d_in[0];
    const float* delta = (const float*)d_in[1];
    const float* h     = (const float*)d_in[2];
    const float* W_sh  = (const float*)d_in[3];
    const float* W_sx  = (const float*)d_in[4];
    const float* W_st  = (const float*)d_in[5];
    const float* b_s   = (const float*)d_in[6];
    const float* WTh   = (const float*)d_in[7];
    const float* WTx   = (const float*)d_in[8];
    const float* WTs   = (const float*)d_in[9];
    const float* b_T   = (const float*)d_in[10];
    const float* W_rh  = (const float*)d_in[11];
    const float* W_rx  = (const float*)d_in[12];
    const float* b_r   = (const float*)d_in[13];
    const float* W_zh  = (const float*)d_in[14];
    const float* W_zx  = (const float*)d_in[15];
    const float* b_z   = (const float*)d_in[16];
    const float* W_h   = (const float*)d_in[17];
    const float* W_x   = (const float*)d_in[18];
    const float* b     = (const float*)d_in[19];
    float* out = (float*)d_out;

    cudaFuncSetAttribute(gemm_s1_fused, cudaFuncAttributeMaxDynamicSharedMemorySize, SM_TOT);
    cudaFuncSetAttribute(gemm_plain,    cudaFuncAttributeMaxDynamicSharedMemorySize, SM_TOT);
    cudaFuncSetAttribute(gemm_ht_fused, cudaFuncAttributeMaxDynamicSharedMemorySize, SM_TOT);

    __nv_bfloat16 *dA2, *dW2, *dx2, *dWx2, *ds2, *drh2, *dWs2, *dWh2;
    float *dC1, *dprehx, *dTadd;
    cudaGetSymbolAddress((void**)&dA2,   g_A2);
    cudaGetSymbolAddress((void**)&dW2,   g_W2);
    cudaGetSymbolAddress((void**)&dx2,   g_x2);
    cudaGetSymbolAddress((void**)&dWx2,  g_Wx2);
    cudaGetSymbolAddress((void**)&ds2,   g_s2);
    cudaGetSymbolAddress((void**)&drh2,  g_rh2);
    cudaGetSymbolAddress((void**)&dWs2,  g_Ws2);
    cudaGetSymbolAddress((void**)&dWh2,  g_Wh2);
    cudaGetSymbolAddress((void**)&dC1,   g_C1);
    cudaGetSymbolAddress((void**)&dprehx,g_prehx);
    cudaGetSymbolAddress((void**)&dTadd, g_Tadd);

    // 1) conversions (2 launches)
    convW_all<<<(NW_ALL + 255) / 256, 256>>>(W_sh, W_sx, WTh, WTx, W_rh, W_rx,
                                             W_zh, W_zx, W_x, WTs, W_h);
    convAct  <<<(NACT + 255) / 256, 256>>>(h, x);

    // 2) stage-1 GEMM + fused ew1 (produces g_s2, g_rh2, C1 gates 1&3)
    gemm_s1_fused<<<dim3(N1 / 256, B_ / 128), NTHR, SM_TOT>>>(
        dA2, dW2, dC1, delta, W_st, b_s, b_r, h);

    // 3) prehx = x2 @ Wx2^T
    gemm_plain<<<dim3(DH / 256, B_ / 128), NTHR, SM_TOT>>>(dx2, dWx2, dprehx, K2_X, DH);

    // 4) Tadd = s2 @ Ws2^T
    gemm_plain<<<dim3(DH / 256, B_ / 128), NTHR, SM_TOT>>>(ds2, dWs2, dTadd, K2_H, DH);

    // 5) ht GEMM + fused ew2 -> final output
    gemm_ht_fused<<<dim3(DH / 256, B_ / 128), NTHR, SM_TOT>>>(
        drh2, dWh2, b_T, b_z, b, h, out);
}